// round 7
// baseline (speedup 1.0000x reference)
#include <cuda_runtime.h>
#include <math.h>
#include <stdint.h>

#define NB    128
#define ND    32
#define NPAIR 16384
#define EPS2  0.25f
#define EPS4  0.0625f
#define PERC  111                // pairs per CTA chunk (ceil(16384/148))
#define RECF4 33                 // float4s per pair record
#define RECB  (RECF4*16)         // 528 bytes
#define SMEMB (PERC*RECB)        // 58608 bytes dynamic smem

typedef unsigned long long u64;

// ---------------- packed f32x2 helpers ---------------------------------------
__device__ __forceinline__ u64 pack2(float lo, float hi) {
    u64 r; asm("mov.b64 %0,{%1,%2};" : "=l"(r) : "f"(lo), "f"(hi)); return r;
}
__device__ __forceinline__ void unpack2(u64 v, float& lo, float& hi) {
    asm("mov.b64 {%0,%1},%2;" : "=f"(lo), "=f"(hi) : "l"(v));
}
__device__ __forceinline__ u64 fma2(u64 a, u64 b, u64 c) {
    u64 d; asm("fma.rn.f32x2 %0,%1,%2,%3;" : "=l"(d) : "l"(a), "l"(b), "l"(c)); return d;
}
__device__ __forceinline__ void lds_v2u64(uint32_t addr, u64& a, u64& b) {
    asm volatile("ld.shared.v2.u64 {%0,%1},[%2];" : "=l"(a), "=l"(b) : "r"(addr));
}
__device__ __forceinline__ uint32_t smem_u32(const void* p) {
    uint32_t a;
    asm("{ .reg .u64 t; cvta.to.shared.u64 t, %1; cvt.u32.u64 %0, t; }" : "=r"(a) : "l"(p));
    return a;
}

// ---------------- device state ------------------------------------------------
// g_sum[b][0..31]=sum W*K, [32..63]=sum W*A, [64]=den. Zero at load; the last
// CTA of every launch re-zeroes it, preserving the invariant across replays.
__device__ float    g_sum[NB * 65];
__device__ unsigned g_ctr;

// ---------------- fused kernel ------------------------------------------------
// grid (148, 2), 256 threads, 2 CTAs/SM. CTA (gx,gy): pair chunk
// [gx*PERC, gx*PERC+cnt) x batches [gy*64, gy*64+64).
// Phase A: compute coefficient records for the chunk straight into smem.
// Phase B: hot loop — per warp: one 32-batch lane-group, 1/4 of the pairs.
// Phase C: CTA reduce (smem) -> global RED -> last CTA finalizes.
__global__ void __launch_bounds__(256, 2)
kfused(const float* __restrict__ X,
       const float* __restrict__ tptr,
       const float* __restrict__ Mu0,
       const float* __restrict__ Mu1,
       const float* __restrict__ S0,
       const float* __restrict__ S1,
       const float* __restrict__ Lam,
       float* __restrict__ out) {
    extern __shared__ __align__(16) float4 srec[];
    __shared__ unsigned sLast;

    const int tid  = threadIdx.x;
    const int lane = tid & 31;
    const int w    = tid >> 5;
    const int gx   = blockIdx.x, gy = blockIdx.y;

    const int pbeg = gx * PERC;
    const int cnt  = min(PERC, NPAIR - pbeg);

    // ---------------- Phase A: inline coefficient prep (lane = dim) ----------
    {
        const float t = tptr[0];
        const float u = 1.f - t;
        const int n = lane;
        for (int local = w; local < cnt; local += 8) {
            int p = pbeg + local;
            int i = p >> 7, j = p & 127;

            float s0 = S0[i * ND + n];
            float s1 = S1[j * ND + n];
            float Ds = sqrtf(fmaf(4.f * s0, s1, EPS4));
            float Cs = 0.5f * (Ds - EPS2);
            float Sigma = u * u * s0 + t * t * s1 + 2.f * t * u * Cs + EPS2 * t * u;
            float St = (t * s1 + u * Cs) - (u * s0 + t * Cs) - EPS2 * t;

            float inv = __fdividef(1.0f, Sigma);
            float K   = St * inv;

            float m0  = Mu0[i * ND + n];
            float m1  = Mu1[j * ND + n];
            float Mut = fmaf(t, m1, u * m0);
            float v   = m1 - m0;

            float a  = -0.5f * inv;
            float bq = Mut * inv;
            float A  = fmaf(-K, Mut, v);

            float cterm = fmaf(a * Mut, Mut, -0.5f * __logf(Sigma));
            #pragma unroll
            for (int o = 16; o; o >>= 1)
                cterm += __shfl_xor_sync(0xffffffffu, cterm, o);

            float aP = __shfl_xor_sync(0xffffffffu, a, 1);
            float bP = __shfl_xor_sync(0xffffffffu, bq, 1);
            float KP = __shfl_xor_sync(0xffffffffu, K, 1);
            float AP = __shfl_xor_sync(0xffffffffu, A, 1);

            float4* r4 = srec + local * RECF4;
            int k = n >> 1;
            if ((n & 1) == 0) r4[k]      = make_float4(a, aP, bq, bP);
            else              r4[16 + k] = make_float4(KP, K, AP, A);
            if (n == 0)       r4[32]     = make_float4(cterm, __ldg(Lam + p), 0.f, 0.f);
        }
    }
    __syncthreads();

    // ---------------- Phase B: hot loop ---------------------------------------
    const int glocal = w >> 2;                  // 0/1: which 32-batch group
    const int slice  = w & 3;                   // pair slice among 4 warps
    const int b      = (gy * 2 + glocal) * 32 + lane;
    const uint32_t sbase = smem_u32(srec);

    u64 xp[16];
    {
        const float4* X4 = reinterpret_cast<const float4*>(X + b * ND);
        #pragma unroll
        for (int q = 0; q < 8; q++) {
            float4 xv = X4[q];
            xp[2 * q]     = pack2(xv.x, xv.y);
            xp[2 * q + 1] = pack2(xv.z, xv.w);
        }
    }
    u64 skp[16], sap[16];
    const u64 zz = pack2(0.f, 0.f);
    #pragma unroll
    for (int k = 0; k < 16; k++) { skp[k] = zz; sap[k] = zz; }
    float den = 0.f;

    for (int j = slice; j < cnt; j += 4) {
        uint32_t rec = sbase + j * RECB;

        u64 lw0 = zz, lw1 = zz;
        #pragma unroll
        for (int k = 0; k < 16; k += 2) {
            u64 ap, bp;
            lds_v2u64(rec + k * 16, ap, bp);
            lw0 = fma2(xp[k], fma2(ap, xp[k], bp), lw0);
            u64 ap1, bp1;
            lds_v2u64(rec + (k + 1) * 16, ap1, bp1);
            lw1 = fma2(xp[k + 1], fma2(ap1, xp[k + 1], bp1), lw1);
        }
        float cl0, cl1;
        asm volatile("ld.shared.v2.f32 {%0,%1},[%2];"
                     : "=f"(cl0), "=f"(cl1) : "r"(rec + 512));
        float a0, a1, b0v, b1v;
        unpack2(lw0, a0, a1);
        unpack2(lw1, b0v, b1v);
        float lw = (a0 + a1) + (b0v + b1v) + cl0;
        lw = fminf(fmaxf(lw, -50.f), 50.f);
        float wt = __expf(lw) * cl1;
        den += wt;
        u64 wtp = pack2(wt, wt);

        #pragma unroll
        for (int k = 0; k < 16; k++) {
            u64 kp, Ap;
            lds_v2u64(rec + 256 + k * 16, kp, Ap);
            skp[k] = fma2(wtp, kp, skp[k]);
            sap[k] = fma2(wtp, Ap, sap[k]);
        }
    }

    // ---------------- Phase C: reduce -----------------------------------------
    __syncthreads();                            // done reading coefficients
    float* red = reinterpret_cast<float*>(srec);   // 64 x 65
    for (int e = tid; e < 64 * 65; e += 256) red[e] = 0.f;
    __syncthreads();

    float* base = red + (glocal * 32 + lane) * 65;   // lane-distinct banks
    #pragma unroll
    for (int k = 0; k < 16; k++) {
        float v0, v1;
        unpack2(skp[k], v0, v1);
        atomicAdd(base + 2 * k,     v0);
        atomicAdd(base + 2 * k + 1, v1);
        unpack2(sap[k], v0, v1);
        atomicAdd(base + 32 + 2 * k,     v0);
        atomicAdd(base + 32 + 2 * k + 1, v1);
    }
    atomicAdd(base + 64, den);
    __syncthreads();

    // CTA partial -> global RED (64 batches x 65 values)
    for (int e = tid; e < 64 * 65; e += 256) {
        int bl  = e / 65;
        int idx = e - bl * 65;
        atomicAdd(&g_sum[(gy * 64 + bl) * 65 + idx], red[e]);
    }

    // ---------------- last CTA finalizes --------------------------------------
    __threadfence();
    if (tid == 0) {
        unsigned old = atomicAdd(&g_ctr, 1u);
        sLast = (old == gridDim.x * gridDim.y - 1) ? 1u : 0u;
    }
    __syncthreads();
    if (sLast) {
        __threadfence();
        volatile const float* vs = g_sum;
        for (int e = tid; e < NB * ND; e += 256) {
            int bb = e >> 5, i = e & 31;
            float sk  = vs[bb * 65 + i];
            float sa  = vs[bb * 65 + 32 + i];
            float dn  = vs[bb * 65 + 64];
            out[e] = fmaf(X[e], sk, sa) / dn;
        }
        __syncthreads();                        // all reads done before re-zero
        for (int e = tid; e < NB * 65; e += 256) g_sum[e] = 0.f;
        __threadfence();
        if (tid == 0) g_ctr = 0u;
    }
}

// ---------------- launch ------------------------------------------------------
extern "C" void kernel_launch(void* const* d_in, const int* in_sizes, int n_in,
                              void* d_out, int out_size) {
    const float* X   = (const float*)d_in[0];
    const float* t   = (const float*)d_in[1];
    const float* Mu0 = (const float*)d_in[2];
    const float* Mu1 = (const float*)d_in[3];
    const float* S0  = (const float*)d_in[4];
    const float* S1  = (const float*)d_in[5];
    const float* Lam = (const float*)d_in[6];
    float* out = (float*)d_out;

    // idempotent; host-side, not stream-ordered -> capture-safe
    cudaFuncSetAttribute(kfused, cudaFuncAttributeMaxDynamicSharedMemorySize, SMEMB);

    dim3 grid(148, 2);
    kfused<<<grid, 256, SMEMB>>>(X, t, Mu0, Mu1, S0, S1, Lam, out);
}